// round 1
// baseline (speedup 1.0000x reference)
#include <cuda_runtime.h>
#include <cuda_bf16.h>

// Bilateral filter 5x5, sigma_xy = sigma_z = 1, zero padding.
// X: [NC, 512, 512] fp32 (NC = n*C = 12), out same shape.
//
// Both gaussians fuse: sim = exp(-0.5*(diff^2 + d2_k))
//                          = exp2(L*diff^2 + L*d2_k), L = -0.5*log2(e).
// One MUFU.EX2 + ~4 FMA-pipe ops per tap. Shared tile (32x8 + halo 2)
// keeps the 25-tap loop branch-free and conflict-free.

#define TX 32
#define TY 8
#define HALO 2
#define SW (TX + 2 * HALO)   // 36
#define SH (TY + 2 * HALO)   // 12

__global__ __launch_bounds__(TX * TY)
void bilateral_kernel(const float* __restrict__ X, float* __restrict__ out)
{
    __shared__ float tile[SH][SW];

    const int H = 512, W = 512;
    const int z = blockIdx.z;
    const float* __restrict__ img = X + (size_t)z * H * W;

    const int gx0 = blockIdx.x * TX - HALO;
    const int gy0 = blockIdx.y * TY - HALO;

    // Cooperative halo load: 432 elements, 256 threads (<=2 iters each).
    const int tid = threadIdx.y * TX + threadIdx.x;
    #pragma unroll
    for (int i = tid; i < SH * SW; i += TX * TY) {
        const int sy = i / SW;
        const int sx = i - sy * SW;
        const int gx = gx0 + sx;
        const int gy = gy0 + sy;
        float v = 0.0f;
        if ((unsigned)gx < (unsigned)W && (unsigned)gy < (unsigned)H)
            v = img[gy * W + gx];
        tile[sy][sx] = v;
    }
    __syncthreads();

    const int tx = threadIdx.x;
    const int ty = threadIdx.y;

    const float c = tile[ty + HALO][tx + HALO];

    // L = -0.5 * log2(e)
    const float L = -0.72134752044448170f;

    float num = 0.0f;
    float den = 0.0f;

    #pragma unroll
    for (int dy = 0; dy < 5; dy++) {
        #pragma unroll
        for (int dx = 0; dx < 5; dx++) {
            const float p = tile[ty + dy][tx + dx];
            const float d = p - c;
            const float u = d * d;
            // d2_k = (dy-2)^2 + (dx-2)^2 is compile-time; L*d2_k folds to a constant.
            const float Ck = L * (float)((dy - 2) * (dy - 2) + (dx - 2) * (dx - 2));
            const float arg = fmaf(u, L, Ck);
            float s;
            asm("ex2.approx.ftz.f32 %0, %1;" : "=f"(s) : "f"(arg));
            num = fmaf(s, p, num);
            den += s;
        }
    }

    const int gx = gx0 + HALO + tx;   // == blockIdx.x*TX + tx, always in range (512 % 32 == 0)
    const int gy = gy0 + HALO + ty;
    out[(size_t)z * H * W + gy * W + gx] = __fdividef(num, den);
}

extern "C" void kernel_launch(void* const* d_in, const int* in_sizes, int n_in,
                              void* d_out, int out_size)
{
    const float* X = (const float*)d_in[0];
    float* out = (float*)d_out;

    const int H = 512, W = 512;
    const int NC = in_sizes[0] / (H * W);   // 12 for (4,3,512,512)

    dim3 block(TX, TY);
    dim3 grid(W / TX, H / TY, NC);
    bilateral_kernel<<<grid, block>>>(X, out);
}

// round 2
// speedup vs baseline: 1.1358x; 1.1358x over previous
#include <cuda_runtime.h>
#include <cuda_bf16.h>

// Bilateral filter 5x5, sigma_xy = sigma_z = 1, zero padding.
// X: [NC, 512, 512] fp32 (NC = 12), out same shape.
//
// R1 -> R2 change: vertical register rolling. Each thread produces KY=4
// outputs in a column. The 5x5 window lives in registers; moving down one
// row reloads only the 5 new taps (LDS/pixel: 25 -> 10 incl. preload).
// Halo load, addressing, prologue amortized 4x. EX2 count unchanged
// (MUFU floor ~17.4us is the next target).

#define TX   32
#define TYW  8          // thread rows per block
#define KY   4          // outputs per thread (vertical)
#define BY   (TYW*KY)   // 32 output rows per block
#define HALO 2
#define SW   (TX + 2*HALO)   // 36
#define SH   (BY + 2*HALO)   // 36

__global__ __launch_bounds__(TX * TYW)
void bilateral_kernel(const float* __restrict__ X, float* __restrict__ out)
{
    __shared__ float tile[SH][SW];

    const int H = 512, W = 512;
    const int z = blockIdx.z;
    const float* __restrict__ img = X + (size_t)z * H * W;

    const int gx0 = blockIdx.x * TX - HALO;
    const int gy0 = blockIdx.y * BY - HALO;

    // Cooperative halo load: 36*36 = 1296 elements, 256 threads (6 iters).
    const int tid = threadIdx.y * TX + threadIdx.x;
    #pragma unroll
    for (int i = tid; i < SH * SW; i += TX * TYW) {
        const int sy = i / SW;
        const int sx = i - sy * SW;
        const int gx = gx0 + sx;
        const int gy = gy0 + sy;
        float v = 0.0f;
        if ((unsigned)gx < (unsigned)W && (unsigned)gy < (unsigned)H)
            v = img[gy * W + gx];
        tile[sy][sx] = v;
    }
    __syncthreads();

    const int tx = threadIdx.x;
    const int ty = threadIdx.y;
    const int row0 = ty * KY;           // first window-top row in tile coords

    // L = -0.5 * log2(e)
    const float L = -0.72134752044448170f;

    // Rolling 5x5 window in registers.
    float w[5][5];
    #pragma unroll
    for (int i = 0; i < 5; i++)
        #pragma unroll
        for (int j = 0; j < 5; j++)
            w[i][j] = tile[row0 + i][tx + j];

    const int gx  = blockIdx.x * TX + tx;
    const int gy1 = blockIdx.y * BY + ty * KY;
    float* __restrict__ o = out + (size_t)z * H * W + gy1 * W + gx;

    #pragma unroll
    for (int r = 0; r < KY; r++) {
        if (r > 0) {
            // slide window down: load new bottom row into the slot that
            // held the (now-expired) top row.
            #pragma unroll
            for (int j = 0; j < 5; j++)
                w[(r - 1) % 5][j] = tile[row0 + r + 4][tx + j];
        }

        const float c = w[(r + 2) % 5][2];
        float num = 0.0f;
        float den = 0.0f;

        #pragma unroll
        for (int dy = 0; dy < 5; dy++) {
            #pragma unroll
            for (int dx = 0; dx < 5; dx++) {
                const float p = w[(r + dy) % 5][dx];
                const float d = p - c;
                const float u = d * d;
                // L*d2_k folds to a compile-time constant.
                const float Ck = L * (float)((dy - 2) * (dy - 2) + (dx - 2) * (dx - 2));
                const float arg = fmaf(u, L, Ck);
                float s;
                asm("ex2.approx.ftz.f32 %0, %1;" : "=f"(s) : "f"(arg));
                num = fmaf(s, p, num);
                den += s;
            }
        }

        o[r * W] = __fdividef(num, den);
    }
}

extern "C" void kernel_launch(void* const* d_in, const int* in_sizes, int n_in,
                              void* d_out, int out_size)
{
    const float* X = (const float*)d_in[0];
    float* out = (float*)d_out;

    const int H = 512, W = 512;
    const int NC = in_sizes[0] / (H * W);   // 12 for (4,3,512,512)

    dim3 block(TX, TYW);
    dim3 grid(W / TX, H / BY, NC);
    bilateral_kernel<<<grid, block>>>(X, out);
}